// round 16
// baseline (speedup 1.0000x reference)
#include <cuda_runtime.h>
#include <math.h>

typedef unsigned long long u64;

#define BB 4
#define RRF 36
#define CCH 3
#define HH 384
#define WW 224
#define KWIN 64
#define SY 321
#define OH 320
#define OW 160
#define NPB (RRF*OH*OW)   /* 1,843,200 per batch */
#define RB1 720
#define RBD 120           /* stageD blocks per batch: 120*96 = 11520 rows */

#define NX 224
#define NKB 113
#define KXP 128
#define NROW_L (BB*CCH*HH)        /* 4608  */
#define NROW_K (BB*RRF*CCH*KWIN)  /* 27648 */
#define NROW_A (BB*RRF*SY)        /* 46224 */

#define LPITCH 8    /* floats per L-plane row = 4 u64. With lb = 5*ty:
                       refill word addr = 40*ty + 8*i + 2*kp; 40 mod 32 = 8
                       -> half-warp banks 8*ty+2*kp distinct -> conflict-free. */

// ---- scratch ----
__device__ float g_resz[(size_t)BB*NPB];
__device__ float g_pmax[BB*RBD];
__device__ float g_psum[BB*RBD];
__device__ float g_bmax[BB];
__device__ float g_binv[BB];

__device__ float g_WcT[NX*KXP];     // TRANSPOSED twiddles: [n][k]
__device__ float g_WsT[NX*KXP];
__device__ float g_Fcs[NKB*80*4];   // fused inverse+x-resize: per (k,p): c0,c1,s0,s1

__device__ float g_Lre[(size_t)NROW_L*KXP];
__device__ float g_Lim[(size_t)NROW_L*KXP];
__device__ float g_Kre[(size_t)NROW_K*KXP];
__device__ float g_Kim[(size_t)NROW_K*KXP];
__device__ float g_Kks[(size_t)NROW_K*KXP];  // kr+ki (Karatsuba plane)
__device__ u64   g_Ari[(size_t)NROW_A*KXP];  // interleaved (re,im) spectra

__device__ __forceinline__ u64 ffma2(u64 a, u64 b, u64 c){
    u64 d;
    asm("fma.rn.f32x2 %0, %1, %2, %3;" : "=l"(d) : "l"(a), "l"(b), "l"(c));
    return d;
}
__device__ __forceinline__ u64 add2(u64 a, u64 b){
    u64 d;
    asm("add.rn.f32x2 %0, %1, %2;" : "=l"(d) : "l"(a), "l"(b));
    return d;
}
__device__ __forceinline__ u64 dup2(float v){
    u64 d; unsigned int u = __float_as_uint(v);
    asm("mov.b64 %0, {%1, %1};" : "=l"(d) : "r"(u));
    return d;
}
__device__ __forceinline__ u64 pack2(unsigned int lo, unsigned int hi){
    u64 d;
    asm("mov.b64 %0, {%1, %2};" : "=l"(d) : "r"(lo), "r"(hi));
    return d;
}
__device__ __forceinline__ void unpack2(u64 v, unsigned int& lo, unsigned int& hi){
    asm("mov.b64 {%0, %1}, %2;" : "=r"(lo), "=r"(hi) : "l"(v));
}

// ---------------------------------------------------------------------------
// Tables
// ---------------------------------------------------------------------------
__global__ void init_tables(){
    int idx = blockIdx.x*256 + threadIdx.x;
    if (idx < NKB*NX){
        int k = idx / NX, n = idx - k*NX;
        int m = (k*n) % NX;
        float a = (float)((2.0*M_PI/(double)NX) * (double)m);
        float c, s;
        sincosf(a, &s, &c);
        g_WcT[n*KXP + k] = c;
        g_WsT[n*KXP + k] = s;
    }
    if (idx < NKB*80){
        int k = idx / 80, p = idx - k*80;
        float sc = ((k==0)||(k==NKB-1)) ? (1.0f/NX) : (2.0f/NX);
        float oc[2], os[2];
#pragma unroll
        for (int e=0; e<2; e++){
            int ox = 2*p + e;
            double tx = ((double)ox + 32.5)*(225.0/224.0) - 0.5;
            double txf = floor(tx);
            int xs = (int)txf - 32;          // in [0,159]
            float fx = (float)(tx - txf);
            int m0 = (k*(xs+32)) % NX, m1 = (k*(xs+33)) % NX;
            float a0 = (float)((2.0*M_PI/(double)NX) * (double)m0);
            float a1 = (float)((2.0*M_PI/(double)NX) * (double)m1);
            float c0, s0, c1, s1;
            sincosf(a0, &s0, &c0);
            sincosf(a1, &s1, &c1);
            int mA = (k*32) % NX;
            float aA = (float)((2.0*M_PI/(double)NX) * (double)mA);
            float cA, sA;
            sincosf(aA, &sA, &cA);
            float c0r = c0*cA + s0*sA, s0r = s0*cA - c0*sA;
            float c1r = c1*cA + s1*sA, s1r = s1*cA - c1*sA;
            oc[e] =  sc*((1.0f-fx)*c0r + fx*c1r);
            os[e] = -sc*((1.0f-fx)*s0r + fx*s1r);
        }
        g_Fcs[idx*4+0] = oc[0];
        g_Fcs[idx*4+1] = oc[1];
        g_Fcs[idx*4+2] = os[0];
        g_Fcs[idx*4+3] = os[1];
    }
}

// ---------------------------------------------------------------------------
// Forward DFT of logits rows — f32x2 packed over row pairs.
// ---------------------------------------------------------------------------
__global__ __launch_bounds__(128) void fwdL(const float* __restrict__ L){
    __shared__ __align__(16) float sx[NX*10];
    const int r0 = blockIdx.x*8;
    const int tid = threadIdx.x;
    for (int t=tid; t<8*NX; t+=128){
        int r = t / NX, n = t - r*NX;
        sx[n*10 + r] = L[(size_t)r0*NX + t];
    }
    __syncthreads();
    u64 ar[4], ai[4];
#pragma unroll
    for (int j=0; j<4; j++){ ar[j]=0ull; ai[j]=0ull; }
#pragma unroll 4
    for (int n=0; n<NX; n++){
        u64 c2 = dup2(g_WcT[n*KXP + tid]);
        u64 s2 = dup2(g_WsT[n*KXP + tid]);
        const u64* xp = (const u64*)(sx + n*10);
#pragma unroll
        for (int j=0; j<4; j++){
            u64 x2 = xp[j];
            ar[j] = ffma2(x2, c2, ar[j]);
            ai[j] = ffma2(x2, s2, ai[j]);
        }
    }
    if (tid < NKB){
#pragma unroll
        for (int j=0; j<4; j++){
            unsigned int lo, hi;
            unpack2(ar[j], lo, hi);
            g_Lre[(size_t)(r0+2*j  )*KXP + tid] = __uint_as_float(lo);
            g_Lre[(size_t)(r0+2*j+1)*KXP + tid] = __uint_as_float(hi);
            unpack2(ai[j], lo, hi);
            g_Lim[(size_t)(r0+2*j  )*KXP + tid] = -__uint_as_float(lo);
            g_Lim[(size_t)(r0+2*j+1)*KXP + tid] = -__uint_as_float(hi);
        }
    }
}

// ---------------------------------------------------------------------------
// Forward DFT of kernel rows — f32x2 packed; stored (kr, ki, kr+ki)
// ---------------------------------------------------------------------------
__global__ __launch_bounds__(128) void fwdK(const float* __restrict__ Kw){
    __shared__ __align__(16) float sx[KWIN*10];
    const int r0 = blockIdx.x*8;
    const int tid = threadIdx.x;
    for (int t=tid; t<8*KWIN; t+=128){
        int r = t / KWIN, n = t - r*KWIN;
        sx[n*10 + r] = Kw[(size_t)r0*KWIN + t];
    }
    __syncthreads();
    u64 ar[4], ai[4];
#pragma unroll
    for (int j=0; j<4; j++){ ar[j]=0ull; ai[j]=0ull; }
#pragma unroll 4
    for (int n=0; n<KWIN; n++){
        u64 c2 = dup2(g_WcT[n*KXP + tid]);
        u64 s2 = dup2(g_WsT[n*KXP + tid]);
        const u64* xp = (const u64*)(sx + n*10);
#pragma unroll
        for (int j=0; j<4; j++){
            u64 x2 = xp[j];
            ar[j] = ffma2(x2, c2, ar[j]);
            ai[j] = ffma2(x2, s2, ai[j]);
        }
    }
    if (tid < NKB){
#pragma unroll
        for (int j=0; j<4; j++){
            unsigned int lo, hi, lo2, hi2;
            unpack2(ar[j], lo, hi);
            unpack2(ai[j], lo2, hi2);
            float r0v = __uint_as_float(lo),  r1v = __uint_as_float(hi);
            float i0v = __uint_as_float(lo2), i1v = __uint_as_float(hi2);
            size_t o0 = (size_t)(r0+2*j  )*KXP + tid;
            size_t o1 = (size_t)(r0+2*j+1)*KXP + tid;
            g_Kre[o0] = r0v;        g_Kre[o1] = r1v;
            g_Kim[o0] = i0v;        g_Kim[o1] = i1v;
            g_Kks[o0] = r0v + i0v;  g_Kks[o1] = r1v + i1v;
        }
    }
}

// ---------------------------------------------------------------------------
// Stage C (R13-proven winner): Karatsuba, d=5, single filter, pitch-4 layout.
// block 256 = 4 kx-pairs x 64 y-threads (5 y' each = 320 rows, zero idle).
// ---------------------------------------------------------------------------
__global__ __launch_bounds__(256,2) void stageC(){
    __shared__ __align__(16) float sLr[392*LPITCH];
    __shared__ __align__(16) float sLi[392*LPITCH];
    __shared__ __align__(16) float sKr[KWIN*8];
    __shared__ __align__(16) float sKi[KWIN*8];
    __shared__ __align__(16) float sKs[KWIN*8];

    const int bf  = blockIdx.y;
    const int b   = bf / RRF;
    const int kx0 = blockIdx.x * 8;
    const int tid = threadIdx.x;
    const int kp  = tid & 3;
    const int ty  = tid >> 2;
    const int lb  = 5*ty;          // 0..315, rows lb..lb+4 all < 320

    u64 M1[5], M2[5], M3[5];
#pragma unroll
    for (int d=0; d<5; d++){ M1[d]=0ull; M2[d]=0ull; M3[d]=0ull; }

    for (int c=0; c<CCH; c++){
        __syncthreads();
        {
            size_t lbase = ((size_t)(b*CCH+c)*HH)*KXP + kx0;
            for (int t=tid; t<392*8; t+=256){
                int y = t>>3, col = t&7;
                int yc = (y < HH) ? y : (HH-1);
                sLr[y*LPITCH+col] = g_Lre[lbase + (size_t)yc*KXP + col];
                sLi[y*LPITCH+col] = g_Lim[lbase + (size_t)yc*KXP + col];
            }
            size_t kbase = ((size_t)(bf*CCH+c)*KWIN)*KXP + kx0;
            for (int t=tid; t<KWIN*8; t+=256){
                int i = t>>3, col = t&7;
                sKr[t] = g_Kre[kbase + (size_t)i*KXP + col];
                sKi[t] = g_Kim[kbase + (size_t)i*KXP + col];
                sKs[t] = g_Kks[kbase + (size_t)i*KXP + col];
            }
        }
        __syncthreads();
        {
            const u64* Lr2 = (const u64*)sLr;   // pitch 4 u64
            const u64* Li2 = (const u64*)sLi;
            const u64* Kr2 = (const u64*)sKr;
            const u64* Ki2 = (const u64*)sKi;
            const u64* Ks2 = (const u64*)sKs;
            u64 wr[8], wi[8], ws[8];
#pragma unroll
            for (int s=0; s<8; s++){
                wr[s] = Lr2[(lb+s)*4 + kp];
                wi[s] = Li2[(lb+s)*4 + kp];
                ws[s] = add2(wr[s], wi[s]);
            }
#pragma unroll 16
            for (int i=0; i<KWIN; i++){
                u64 kr = Kr2[i*4+kp], ki = Ki2[i*4+kp], ks = Ks2[i*4+kp];
#pragma unroll
                for (int d=0; d<5; d++){
                    int s = (i+d)&7;
                    M1[d] = ffma2(wr[s], kr, M1[d]);
                    M2[d] = ffma2(wi[s], ki, M2[d]);
                    M3[d] = ffma2(ws[s], ks, M3[d]);
                }
                int s2 = i&7;                       // slot of row lb+i, retired
                u64 nr = Lr2[(lb+i+8)*4 + kp];      // rows <= 315+71 = 386 < 392
                u64 ni = Li2[(lb+i+8)*4 + kp];
                wr[s2] = nr;
                wi[s2] = ni;
                ws[s2] = add2(nr, ni);
            }
        }
    }
#pragma unroll
    for (int d=0; d<5; d++){
        unsigned int a, bb2;
        unpack2(M1[d], a, bb2);
        float m1l = __uint_as_float(a), m1h = __uint_as_float(bb2);
        unpack2(M2[d], a, bb2);
        float m2l = __uint_as_float(a), m2h = __uint_as_float(bb2);
        unpack2(M3[d], a, bb2);
        float m3l = __uint_as_float(a), m3h = __uint_as_float(bb2);
        float arl = m1l - m2l,       arh = m1h - m2h;
        float ail = m3l - m1l - m2l, aih = m3h - m1h - m2h;
        size_t row = (size_t)bf*SY + lb + d;
        uint4 o;
        o.x = __float_as_uint(arl); o.y = __float_as_uint(ail);
        o.z = __float_as_uint(arh); o.w = __float_as_uint(aih);
        *(uint4*)&g_Ari[row*KXP + kx0 + 2*kp] = o;
    }
}

// ---------------------------------------------------------------------------
// Edge: row y'=320 for all (bf, kx). 144 blocks x 128 thr.
// ---------------------------------------------------------------------------
__global__ __launch_bounds__(128) void edge320(){
    const int bf = blockIdx.x;
    const int b  = bf / RRF;
    const int k  = threadIdx.x;
    if (k >= NKB) return;
    float are = 0.f, aie = 0.f;
    for (int c=0; c<CCH; c++){
        const float* Lr = g_Lre + ((size_t)(b*CCH+c)*HH + 320)*KXP + k;
        const float* Li = g_Lim + ((size_t)(b*CCH+c)*HH + 320)*KXP + k;
        const float* Kr = g_Kre + ((size_t)(bf*CCH+c)*KWIN)*KXP + k;
        const float* Ki = g_Kim + ((size_t)(bf*CCH+c)*KWIN)*KXP + k;
#pragma unroll 8
        for (int i=0; i<KWIN; i++){
            float lr = Lr[(size_t)i*KXP], li = Li[(size_t)i*KXP];
            float kr = Kr[(size_t)i*KXP], ki = Ki[(size_t)i*KXP];
            are = fmaf(lr, kr, fmaf(-li, ki, are));
            aie = fmaf(lr, ki, fmaf( li, kr, aie));
        }
    }
    g_Ari[((size_t)bf*SY + 320)*KXP + k] = pack2(__float_as_uint(are), __float_as_uint(aie));
}

// ---------------------------------------------------------------------------
// Stage D v2: 6 rows per thread -> table loads amortized, FMA-bound.
// block 256 = 16 px-threads (5 x-pairs) x 16 rowgroups (6 rows) = 96 rows.
// grid (120, BB).
// ---------------------------------------------------------------------------
#define DRW 96
#define KC  16
__global__ __launch_bounds__(256,1) void stageD(){
    __shared__ u64   sSp[DRW*NKB];   // ~86.8KB
    __shared__ uint4 sTab[KC*80];    // 20KB
    __shared__ int   sYS[DRW];
    __shared__ float sFY[DRW];
    __shared__ float red[256];

    const int b   = blockIdx.y;
    const int r0  = blockIdx.x * DRW;
    const int tid = threadIdx.x;

    if (tid < DRW){
        int oy = (r0 + tid) % OH;
        float ty = ((float)oy + 32.5f)*(385.0f/384.0f) - 0.5f;
        float yf = floorf(ty);
        sYS[tid] = (int)yf - 32;
        sFY[tid] = ty - yf;
    }
    __syncthreads();

    for (int t=tid; t<DRW*NKB; t+=256){
        int rr = t / NKB, k = t - rr*NKB;
        int r  = r0 + rr;
        int f  = r / OH;
        size_t arow = ((size_t)(b*RRF + f))*SY + sYS[rr];
        u64 v0 = g_Ari[arow*KXP + k];
        u64 v1 = g_Ari[(arow+1)*KXP + k];
        float fy = sFY[rr];
        unsigned int l0,h0,l1,h1;
        unpack2(v0, l0, h0); unpack2(v1, l1, h1);
        float re0=__uint_as_float(l0), im0=__uint_as_float(h0);
        float re1=__uint_as_float(l1), im1=__uint_as_float(h1);
        float re = re0 + fy*(re1-re0);
        float im = im0 + fy*(im1-im0);
        sSp[t] = pack2(__float_as_uint(re), __float_as_uint(im));
    }

    const int px = tid & 15;
    const int rg = tid >> 4;
    const uint4* F4 = (const uint4*)g_Fcs;
    const u64* sp = sSp + (rg*6)*NKB;

    u64 acc[6][5];
#pragma unroll
    for (int rr=0; rr<6; rr++)
#pragma unroll
        for (int q=0; q<5; q++) acc[rr][q] = 0ull;

    for (int kc0=0; kc0<NKB; kc0+=KC){
        const int kn = (NKB - kc0 < KC) ? (NKB - kc0) : KC;
        __syncthreads();
        for (int t=tid; t<kn*80; t+=256) sTab[t] = F4[kc0*80 + t];
        __syncthreads();
        for (int kk=0; kk<kn; kk++){
            u64 cc[5], ss[5];
#pragma unroll
            for (int q=0; q<5; q++){
                uint4 v = sTab[kk*80 + px + 16*q];
                cc[q] = pack2(v.x, v.y);
                ss[q] = pack2(v.z, v.w);
            }
            const int k = kc0 + kk;
#pragma unroll
            for (int rr=0; rr<6; rr++){
                u64 sv = sp[rr*NKB + k];
                unsigned int lo, hi;
                unpack2(sv, lo, hi);
                u64 re2 = dup2(__uint_as_float(lo));
                u64 im2 = dup2(__uint_as_float(hi));
#pragma unroll
                for (int q=0; q<5; q++)
                    acc[rr][q] = ffma2(re2, cc[q], ffma2(im2, ss[q], acc[rr][q]));
            }
        }
    }

    float lmax = -3.0e38f;
#pragma unroll
    for (int rr=0; rr<6; rr++){
        int r = r0 + rg*6 + rr;
#pragma unroll
        for (int q=0; q<5; q++){
            int p = px + 16*q;
            *(u64*)&g_resz[(size_t)b*NPB + (size_t)r*OW + 2*p] = acc[rr][q];
            unsigned int lo, hi;
            unpack2(acc[rr][q], lo, hi);
            lmax = fmaxf(lmax, fmaxf(__uint_as_float(lo), __uint_as_float(hi)));
        }
    }
    __syncthreads();
    red[tid] = lmax; __syncthreads();
    for (int s=128; s>0; s>>=1){
        if (tid < s) red[tid] = fmaxf(red[tid], red[tid+s]);
        __syncthreads();
    }
    const float bm = red[0];
    __syncthreads();

    float ls = 0.0f;
#pragma unroll
    for (int rr=0; rr<6; rr++)
#pragma unroll
        for (int q=0; q<5; q++){
            unsigned int lo, hi;
            unpack2(acc[rr][q], lo, hi);
            ls += expf(__uint_as_float(lo) - bm);
            ls += expf(__uint_as_float(hi) - bm);
        }
    red[tid] = ls; __syncthreads();
    for (int s=128; s>0; s>>=1){
        if (tid < s) red[tid] += red[tid+s];
        __syncthreads();
    }
    if (tid == 0){
        g_pmax[b*RBD + blockIdx.x] = bm;
        g_psum[b*RBD + blockIdx.x] = red[0];
    }
}

// ---------------------------------------------------------------------------
// Combine partials + final normalize
// ---------------------------------------------------------------------------
__global__ void combine_kernel(){
    const int b = blockIdx.x;
    const int tid = threadIdx.x;
    __shared__ float red[256];
    float m = -3.0e38f;
    for (int i = tid; i < RBD; i += 256) m = fmaxf(m, g_pmax[b*RBD + i]);
    red[tid] = m; __syncthreads();
    for (int s = 128; s > 0; s >>= 1){
        if (tid < s) red[tid] = fmaxf(red[tid], red[tid+s]);
        __syncthreads();
    }
    const float gm = red[0];
    __syncthreads();
    float ssum = 0.0f;
    for (int i = tid; i < RBD; i += 256)
        ssum += g_psum[b*RBD + i] * expf(g_pmax[b*RBD + i] - gm);
    red[tid] = ssum; __syncthreads();
    for (int s = 128; s > 0; s >>= 1){
        if (tid < s) red[tid] += red[tid+s];
        __syncthreads();
    }
    if (tid == 0){
        g_bmax[b] = gm;
        g_binv[b] = 1.0f / red[0];
    }
}

__global__ void final_kernel(float* __restrict__ out){
    const int b = blockIdx.y;
    const float bm  = g_bmax[b];
    const float inv = g_binv[b];
    const int base = blockIdx.x * (256*10);
#pragma unroll
    for (int t = 0; t < 10; t++){
        int idx = base + t*256 + threadIdx.x;
        out[(size_t)b*NPB + idx] = expf(g_resz[(size_t)b*NPB + idx] - bm) * inv;
    }
}

extern "C" void kernel_launch(void* const* d_in, const int* in_sizes, int n_in,
                              void* d_out, int out_size){
    const float* L  = (const float*)d_in[0];   // logits (4,3,384,224)
    const float* Kw = (const float*)d_in[1];   // kernel (144,3,64,64)
    float* out = (float*)d_out;                // (4,36,320,160) f32

    init_tables<<<99, 256>>>();
    fwdL<<<NROW_L/8, 128>>>(L);
    fwdK<<<NROW_K/8, 128>>>(Kw);
    stageC<<<dim3(15, BB*RRF), 256>>>();
    edge320<<<BB*RRF, 128>>>();
    stageD<<<dim3(RBD, BB), 256>>>();
    combine_kernel<<<4, 256>>>();
    final_kernel<<<dim3(RB1, 4), 256>>>(out);
}

// round 17
// speedup vs baseline: 1.1163x; 1.1163x over previous
#include <cuda_runtime.h>
#include <math.h>

typedef unsigned long long u64;

#define BB 4
#define RRF 36
#define CCH 3
#define HH 384
#define WW 224
#define KWIN 64
#define SY 321
#define OH 320
#define OW 160
#define NPB (RRF*OH*OW)   /* 1,843,200 per batch */
#define RB1 720
#define RBD 240           /* stageD blocks per batch: 240*48 = 11520 rows */

#define NX 224
#define NKB 113
#define KXP 128
#define NROW_L (BB*CCH*HH)        /* 4608  */
#define NROW_K (BB*RRF*CCH*KWIN)  /* 27648 */
#define NROW_A (BB*RRF*SY)        /* 46224 */

#define LPITCH 8    /* floats per L-plane row = 4 u64. With lb = 5*ty:
                       refill word addr = 40*ty + 8*i + 2*kp; 40 mod 32 = 8
                       -> half-warp banks 8*ty+2*kp distinct -> conflict-free. */

// ---- scratch ----
__device__ float g_resz[(size_t)BB*NPB];
__device__ float g_pmax[BB*RBD];
__device__ float g_psum[BB*RBD];
__device__ float g_bmax[BB];
__device__ float g_binv[BB];

__device__ float g_WcT[NX*KXP];     // TRANSPOSED twiddles: [n][k]
__device__ float g_WsT[NX*KXP];
__device__ float g_Fcs[NKB*80*4];   // fused inverse+x-resize: per (k,p): c0,c1,s0,s1

__device__ float g_Lre[(size_t)NROW_L*KXP];
__device__ float g_Lim[(size_t)NROW_L*KXP];
__device__ float g_Kre[(size_t)NROW_K*KXP];
__device__ float g_Kim[(size_t)NROW_K*KXP];
__device__ float g_Kks[(size_t)NROW_K*KXP];  // kr+ki (Karatsuba plane)
__device__ u64   g_Ari[(size_t)NROW_A*KXP];  // interleaved (re,im) spectra

__device__ __forceinline__ u64 ffma2(u64 a, u64 b, u64 c){
    u64 d;
    asm("fma.rn.f32x2 %0, %1, %2, %3;" : "=l"(d) : "l"(a), "l"(b), "l"(c));
    return d;
}
__device__ __forceinline__ u64 add2(u64 a, u64 b){
    u64 d;
    asm("add.rn.f32x2 %0, %1, %2;" : "=l"(d) : "l"(a), "l"(b));
    return d;
}
__device__ __forceinline__ u64 dup2(float v){
    u64 d; unsigned int u = __float_as_uint(v);
    asm("mov.b64 %0, {%1, %1};" : "=l"(d) : "r"(u));
    return d;
}
__device__ __forceinline__ u64 pack2(unsigned int lo, unsigned int hi){
    u64 d;
    asm("mov.b64 %0, {%1, %2};" : "=l"(d) : "r"(lo), "r"(hi));
    return d;
}
__device__ __forceinline__ void unpack2(u64 v, unsigned int& lo, unsigned int& hi){
    asm("mov.b64 {%0, %1}, %2;" : "=r"(lo), "=r"(hi) : "l"(v));
}

// ---------------------------------------------------------------------------
// Tables
// ---------------------------------------------------------------------------
__global__ void init_tables(){
    int idx = blockIdx.x*256 + threadIdx.x;
    if (idx < NKB*NX){
        int k = idx / NX, n = idx - k*NX;
        int m = (k*n) % NX;
        float a = (float)((2.0*M_PI/(double)NX) * (double)m);
        float c, s;
        sincosf(a, &s, &c);
        g_WcT[n*KXP + k] = c;
        g_WsT[n*KXP + k] = s;
    }
    if (idx < NKB*80){
        int k = idx / 80, p = idx - k*80;
        float sc = ((k==0)||(k==NKB-1)) ? (1.0f/NX) : (2.0f/NX);
        float oc[2], os[2];
#pragma unroll
        for (int e=0; e<2; e++){
            int ox = 2*p + e;
            double tx = ((double)ox + 32.5)*(225.0/224.0) - 0.5;
            double txf = floor(tx);
            int xs = (int)txf - 32;          // in [0,159]
            float fx = (float)(tx - txf);
            int m0 = (k*(xs+32)) % NX, m1 = (k*(xs+33)) % NX;
            float a0 = (float)((2.0*M_PI/(double)NX) * (double)m0);
            float a1 = (float)((2.0*M_PI/(double)NX) * (double)m1);
            float c0, s0, c1, s1;
            sincosf(a0, &s0, &c0);
            sincosf(a1, &s1, &c1);
            int mA = (k*32) % NX;
            float aA = (float)((2.0*M_PI/(double)NX) * (double)mA);
            float cA, sA;
            sincosf(aA, &sA, &cA);
            float c0r = c0*cA + s0*sA, s0r = s0*cA - c0*sA;
            float c1r = c1*cA + s1*sA, s1r = s1*cA - c1*sA;
            oc[e] =  sc*((1.0f-fx)*c0r + fx*c1r);
            os[e] = -sc*((1.0f-fx)*s0r + fx*s1r);
        }
        g_Fcs[idx*4+0] = oc[0];
        g_Fcs[idx*4+1] = oc[1];
        g_Fcs[idx*4+2] = os[0];
        g_Fcs[idx*4+3] = os[1];
    }
}

// ---------------------------------------------------------------------------
// Forward DFT of logits rows — f32x2 packed over row pairs.
// ---------------------------------------------------------------------------
__global__ __launch_bounds__(128) void fwdL(const float* __restrict__ L){
    __shared__ __align__(16) float sx[NX*10];
    const int r0 = blockIdx.x*8;
    const int tid = threadIdx.x;
    for (int t=tid; t<8*NX; t+=128){
        int r = t / NX, n = t - r*NX;
        sx[n*10 + r] = L[(size_t)r0*NX + t];
    }
    __syncthreads();
    u64 ar[4], ai[4];
#pragma unroll
    for (int j=0; j<4; j++){ ar[j]=0ull; ai[j]=0ull; }
#pragma unroll 4
    for (int n=0; n<NX; n++){
        u64 c2 = dup2(g_WcT[n*KXP + tid]);
        u64 s2 = dup2(g_WsT[n*KXP + tid]);
        const u64* xp = (const u64*)(sx + n*10);
#pragma unroll
        for (int j=0; j<4; j++){
            u64 x2 = xp[j];
            ar[j] = ffma2(x2, c2, ar[j]);
            ai[j] = ffma2(x2, s2, ai[j]);
        }
    }
    if (tid < NKB){
#pragma unroll
        for (int j=0; j<4; j++){
            unsigned int lo, hi;
            unpack2(ar[j], lo, hi);
            g_Lre[(size_t)(r0+2*j  )*KXP + tid] = __uint_as_float(lo);
            g_Lre[(size_t)(r0+2*j+1)*KXP + tid] = __uint_as_float(hi);
            unpack2(ai[j], lo, hi);
            g_Lim[(size_t)(r0+2*j  )*KXP + tid] = -__uint_as_float(lo);
            g_Lim[(size_t)(r0+2*j+1)*KXP + tid] = -__uint_as_float(hi);
        }
    }
}

// ---------------------------------------------------------------------------
// Forward DFT of kernel rows — f32x2 packed; stored (kr, ki, kr+ki)
// ---------------------------------------------------------------------------
__global__ __launch_bounds__(128) void fwdK(const float* __restrict__ Kw){
    __shared__ __align__(16) float sx[KWIN*10];
    const int r0 = blockIdx.x*8;
    const int tid = threadIdx.x;
    for (int t=tid; t<8*KWIN; t+=128){
        int r = t / KWIN, n = t - r*KWIN;
        sx[n*10 + r] = Kw[(size_t)r0*KWIN + t];
    }
    __syncthreads();
    u64 ar[4], ai[4];
#pragma unroll
    for (int j=0; j<4; j++){ ar[j]=0ull; ai[j]=0ull; }
#pragma unroll 4
    for (int n=0; n<KWIN; n++){
        u64 c2 = dup2(g_WcT[n*KXP + tid]);
        u64 s2 = dup2(g_WsT[n*KXP + tid]);
        const u64* xp = (const u64*)(sx + n*10);
#pragma unroll
        for (int j=0; j<4; j++){
            u64 x2 = xp[j];
            ar[j] = ffma2(x2, c2, ar[j]);
            ai[j] = ffma2(x2, s2, ai[j]);
        }
    }
    if (tid < NKB){
#pragma unroll
        for (int j=0; j<4; j++){
            unsigned int lo, hi, lo2, hi2;
            unpack2(ar[j], lo, hi);
            unpack2(ai[j], lo2, hi2);
            float r0v = __uint_as_float(lo),  r1v = __uint_as_float(hi);
            float i0v = __uint_as_float(lo2), i1v = __uint_as_float(hi2);
            size_t o0 = (size_t)(r0+2*j  )*KXP + tid;
            size_t o1 = (size_t)(r0+2*j+1)*KXP + tid;
            g_Kre[o0] = r0v;        g_Kre[o1] = r1v;
            g_Kim[o0] = i0v;        g_Kim[o1] = i1v;
            g_Kks[o0] = r0v + i0v;  g_Kks[o1] = r1v + i1v;
        }
    }
}

// ---------------------------------------------------------------------------
// Stage C (R13-proven winner): Karatsuba, d=5, single filter, pitch-4 layout.
// block 256 = 4 kx-pairs x 64 y-threads (5 y' each = 320 rows, zero idle).
// ---------------------------------------------------------------------------
__global__ __launch_bounds__(256,2) void stageC(){
    __shared__ __align__(16) float sLr[392*LPITCH];
    __shared__ __align__(16) float sLi[392*LPITCH];
    __shared__ __align__(16) float sKr[KWIN*8];
    __shared__ __align__(16) float sKi[KWIN*8];
    __shared__ __align__(16) float sKs[KWIN*8];

    const int bf  = blockIdx.y;
    const int b   = bf / RRF;
    const int kx0 = blockIdx.x * 8;
    const int tid = threadIdx.x;
    const int kp  = tid & 3;
    const int ty  = tid >> 2;
    const int lb  = 5*ty;          // 0..315, rows lb..lb+4 all < 320

    u64 M1[5], M2[5], M3[5];
#pragma unroll
    for (int d=0; d<5; d++){ M1[d]=0ull; M2[d]=0ull; M3[d]=0ull; }

    for (int c=0; c<CCH; c++){
        __syncthreads();
        {
            size_t lbase = ((size_t)(b*CCH+c)*HH)*KXP + kx0;
            for (int t=tid; t<392*8; t+=256){
                int y = t>>3, col = t&7;
                int yc = (y < HH) ? y : (HH-1);
                sLr[y*LPITCH+col] = g_Lre[lbase + (size_t)yc*KXP + col];
                sLi[y*LPITCH+col] = g_Lim[lbase + (size_t)yc*KXP + col];
            }
            size_t kbase = ((size_t)(bf*CCH+c)*KWIN)*KXP + kx0;
            for (int t=tid; t<KWIN*8; t+=256){
                int i = t>>3, col = t&7;
                sKr[t] = g_Kre[kbase + (size_t)i*KXP + col];
                sKi[t] = g_Kim[kbase + (size_t)i*KXP + col];
                sKs[t] = g_Kks[kbase + (size_t)i*KXP + col];
            }
        }
        __syncthreads();
        {
            const u64* Lr2 = (const u64*)sLr;   // pitch 4 u64
            const u64* Li2 = (const u64*)sLi;
            const u64* Kr2 = (const u64*)sKr;
            const u64* Ki2 = (const u64*)sKi;
            const u64* Ks2 = (const u64*)sKs;
            u64 wr[8], wi[8], ws[8];
#pragma unroll
            for (int s=0; s<8; s++){
                wr[s] = Lr2[(lb+s)*4 + kp];
                wi[s] = Li2[(lb+s)*4 + kp];
                ws[s] = add2(wr[s], wi[s]);
            }
#pragma unroll 16
            for (int i=0; i<KWIN; i++){
                u64 kr = Kr2[i*4+kp], ki = Ki2[i*4+kp], ks = Ks2[i*4+kp];
#pragma unroll
                for (int d=0; d<5; d++){
                    int s = (i+d)&7;
                    M1[d] = ffma2(wr[s], kr, M1[d]);
                    M2[d] = ffma2(wi[s], ki, M2[d]);
                    M3[d] = ffma2(ws[s], ks, M3[d]);
                }
                int s2 = i&7;                       // slot of row lb+i, retired
                u64 nr = Lr2[(lb+i+8)*4 + kp];      // rows <= 315+71 = 386 < 392
                u64 ni = Li2[(lb+i+8)*4 + kp];
                wr[s2] = nr;
                wi[s2] = ni;
                ws[s2] = add2(nr, ni);
            }
        }
    }
#pragma unroll
    for (int d=0; d<5; d++){
        unsigned int a, bb2;
        unpack2(M1[d], a, bb2);
        float m1l = __uint_as_float(a), m1h = __uint_as_float(bb2);
        unpack2(M2[d], a, bb2);
        float m2l = __uint_as_float(a), m2h = __uint_as_float(bb2);
        unpack2(M3[d], a, bb2);
        float m3l = __uint_as_float(a), m3h = __uint_as_float(bb2);
        float arl = m1l - m2l,       arh = m1h - m2h;
        float ail = m3l - m1l - m2l, aih = m3h - m1h - m2h;
        size_t row = (size_t)bf*SY + lb + d;
        uint4 o;
        o.x = __float_as_uint(arl); o.y = __float_as_uint(ail);
        o.z = __float_as_uint(arh); o.w = __float_as_uint(aih);
        *(uint4*)&g_Ari[row*KXP + kx0 + 2*kp] = o;
    }
}

// ---------------------------------------------------------------------------
// Edge: row y'=320 for all (bf, kx). 144 blocks x 128 thr.
// ---------------------------------------------------------------------------
__global__ __launch_bounds__(128) void edge320(){
    const int bf = blockIdx.x;
    const int b  = bf / RRF;
    const int k  = threadIdx.x;
    if (k >= NKB) return;
    float are = 0.f, aie = 0.f;
    for (int c=0; c<CCH; c++){
        const float* Lr = g_Lre + ((size_t)(b*CCH+c)*HH + 320)*KXP + k;
        const float* Li = g_Lim + ((size_t)(b*CCH+c)*HH + 320)*KXP + k;
        const float* Kr = g_Kre + ((size_t)(bf*CCH+c)*KWIN)*KXP + k;
        const float* Ki = g_Kim + ((size_t)(bf*CCH+c)*KWIN)*KXP + k;
#pragma unroll 8
        for (int i=0; i<KWIN; i++){
            float lr = Lr[(size_t)i*KXP], li = Li[(size_t)i*KXP];
            float kr = Kr[(size_t)i*KXP], ki = Ki[(size_t)i*KXP];
            are = fmaf(lr, kr, fmaf(-li, ki, are));
            aie = fmaf(lr, ki, fmaf( li, kr, aie));
        }
    }
    g_Ari[((size_t)bf*SY + 320)*KXP + k] = pack2(__float_as_uint(are), __float_as_uint(aie));
}

// ---------------------------------------------------------------------------
// Stage D (R13-proven): y-blend + inverse DFT + x-resize tables + softmax
// partials. block 256 = 16 px-threads x 16 rowgroups (3 rows) = 48 rows.
// ---------------------------------------------------------------------------
#define DRW 48
#define KC  16
__global__ __launch_bounds__(256,2) void stageD(){
    __shared__ u64   sSp[DRW*NKB];
    __shared__ uint4 sTab[KC*80];
    __shared__ int   sYS[DRW];
    __shared__ float sFY[DRW];
    __shared__ float red[256];

    const int b   = blockIdx.y;
    const int r0  = blockIdx.x * DRW;
    const int tid = threadIdx.x;

    if (tid < DRW){
        int oy = (r0 + tid) % OH;
        float ty = ((float)oy + 32.5f)*(385.0f/384.0f) - 0.5f;
        float yf = floorf(ty);
        sYS[tid] = (int)yf - 32;
        sFY[tid] = ty - yf;
    }
    __syncthreads();

    for (int t=tid; t<DRW*NKB; t+=256){
        int rr = t / NKB, k = t - rr*NKB;
        int r  = r0 + rr;
        int f  = r / OH;
        size_t arow = ((size_t)(b*RRF + f))*SY + sYS[rr];
        u64 v0 = g_Ari[arow*KXP + k];
        u64 v1 = g_Ari[(arow+1)*KXP + k];
        float fy = sFY[rr];
        unsigned int l0,h0,l1,h1;
        unpack2(v0, l0, h0); unpack2(v1, l1, h1);
        float re0=__uint_as_float(l0), im0=__uint_as_float(h0);
        float re1=__uint_as_float(l1), im1=__uint_as_float(h1);
        float re = re0 + fy*(re1-re0);
        float im = im0 + fy*(im1-im0);
        sSp[t] = pack2(__float_as_uint(re), __float_as_uint(im));
    }

    const int px = tid & 15;
    const int rg = tid >> 4;
    const uint4* F4 = (const uint4*)g_Fcs;
    const u64* sp = sSp + (rg*3)*NKB;

    u64 acc[3][5];
#pragma unroll
    for (int rr=0; rr<3; rr++)
#pragma unroll
        for (int q=0; q<5; q++) acc[rr][q] = 0ull;

    for (int kc0=0; kc0<NKB; kc0+=KC){
        const int kn = (NKB - kc0 < KC) ? (NKB - kc0) : KC;
        __syncthreads();
        for (int t=tid; t<kn*80; t+=256) sTab[t] = F4[kc0*80 + t];
        __syncthreads();
#pragma unroll 2
        for (int kk=0; kk<kn; kk++){
            u64 cc[5], ss[5];
#pragma unroll
            for (int q=0; q<5; q++){
                uint4 v = sTab[kk*80 + px + 16*q];
                cc[q] = pack2(v.x, v.y);
                ss[q] = pack2(v.z, v.w);
            }
            const int k = kc0 + kk;
#pragma unroll
            for (int rr=0; rr<3; rr++){
                u64 sv = sp[rr*NKB + k];
                unsigned int lo, hi;
                unpack2(sv, lo, hi);
                u64 re2 = dup2(__uint_as_float(lo));
                u64 im2 = dup2(__uint_as_float(hi));
#pragma unroll
                for (int q=0; q<5; q++)
                    acc[rr][q] = ffma2(re2, cc[q], ffma2(im2, ss[q], acc[rr][q]));
            }
        }
    }

    float lmax = -3.0e38f;
#pragma unroll
    for (int rr=0; rr<3; rr++){
        int r = r0 + rg*3 + rr;
#pragma unroll
        for (int q=0; q<5; q++){
            int p = px + 16*q;
            *(u64*)&g_resz[(size_t)b*NPB + (size_t)r*OW + 2*p] = acc[rr][q];
            unsigned int lo, hi;
            unpack2(acc[rr][q], lo, hi);
            lmax = fmaxf(lmax, fmaxf(__uint_as_float(lo), __uint_as_float(hi)));
        }
    }
    __syncthreads();
    red[tid] = lmax; __syncthreads();
    for (int s=128; s>0; s>>=1){
        if (tid < s) red[tid] = fmaxf(red[tid], red[tid+s]);
        __syncthreads();
    }
    const float bm = red[0];
    __syncthreads();

    float ls = 0.0f;
#pragma unroll
    for (int rr=0; rr<3; rr++)
#pragma unroll
        for (int q=0; q<5; q++){
            unsigned int lo, hi;
            unpack2(acc[rr][q], lo, hi);
            ls += expf(__uint_as_float(lo) - bm);
            ls += expf(__uint_as_float(hi) - bm);
        }
    red[tid] = ls; __syncthreads();
    for (int s=128; s>0; s>>=1){
        if (tid < s) red[tid] += red[tid+s];
        __syncthreads();
    }
    if (tid == 0){
        g_pmax[b*RBD + blockIdx.x] = bm;
        g_psum[b*RBD + blockIdx.x] = red[0];
    }
}

// ---------------------------------------------------------------------------
// Combine partials + final normalize
// ---------------------------------------------------------------------------
__global__ void combine_kernel(){
    const int b = blockIdx.x;
    const int tid = threadIdx.x;
    __shared__ float red[256];
    float m = -3.0e38f;
    for (int i = tid; i < RBD; i += 256) m = fmaxf(m, g_pmax[b*RBD + i]);
    red[tid] = m; __syncthreads();
    for (int s = 128; s > 0; s >>= 1){
        if (tid < s) red[tid] = fmaxf(red[tid], red[tid+s]);
        __syncthreads();
    }
    const float gm = red[0];
    __syncthreads();
    float ssum = 0.0f;
    for (int i = tid; i < RBD; i += 256)
        ssum += g_psum[b*RBD + i] * expf(g_pmax[b*RBD + i] - gm);
    red[tid] = ssum; __syncthreads();
    for (int s = 128; s > 0; s >>= 1){
        if (tid < s) red[tid] += red[tid+s];
        __syncthreads();
    }
    if (tid == 0){
        g_bmax[b] = gm;
        g_binv[b] = 1.0f / red[0];
    }
}

__global__ void final_kernel(float* __restrict__ out){
    const int b = blockIdx.y;
    const float bm  = g_bmax[b];
    const float inv = g_binv[b];
    const int base = blockIdx.x * (256*10);
#pragma unroll
    for (int t = 0; t < 10; t++){
        int idx = base + t*256 + threadIdx.x;
        out[(size_t)b*NPB + idx] = expf(g_resz[(size_t)b*NPB + idx] - bm) * inv;
    }
}

extern "C" void kernel_launch(void* const* d_in, const int* in_sizes, int n_in,
                              void* d_out, int out_size){
    const float* L  = (const float*)d_in[0];   // logits (4,3,384,224)
    const float* Kw = (const float*)d_in[1];   // kernel (144,3,64,64)
    float* out = (float*)d_out;                // (4,36,320,160) f32

    init_tables<<<99, 256>>>();
    fwdL<<<NROW_L/8, 128>>>(L);
    fwdK<<<NROW_K/8, 128>>>(Kw);
    stageC<<<dim3(15, BB*RRF), 256>>>();
    edge320<<<BB*RRF, 128>>>();
    stageD<<<dim3(RBD, BB), 256>>>();
    combine_kernel<<<4, 256>>>();
    final_kernel<<<dim3(RB1, 4), 256>>>(out);
}